// round 6
// baseline (speedup 1.0000x reference)
#include <cuda_runtime.h>
#include <cstdint>
#include <cstdio>

// ---------------------------------------------------------------------------
// GraphFusionLayerAtt: fully-fused fp32 pipeline (f32x2 packed FMA).
//   Identity GAT path for all batch elements; batch 0 fixed up by a small
//   parallel kernel that recomputes the true 2x2 GAT attention for nodes {0,1}.
// ---------------------------------------------------------------------------

typedef unsigned long long u64;

__device__ __forceinline__ u64 pack2(float x, float y) {
    u64 r; asm("mov.b64 %0, {%1, %2};" : "=l"(r) : "f"(x), "f"(y)); return r;
}
__device__ __forceinline__ u64 fma2(u64 a, u64 b, u64 c) {
    u64 d; asm("fma.rn.f32x2 %0, %1, %2, %3;" : "=l"(d) : "l"(a), "l"(b), "l"(c)); return d;
}
__device__ __forceinline__ float2 unpk(u64 v) {
    float2 f; asm("mov.b64 {%0, %1}, %2;" : "=f"(f.x), "=f"(f.y) : "l"(v)); return f;
}

static constexpr int H      = 256;
static constexpr int MB     = 32;     // batch elements per CTA
static constexpr int NTHR   = 512;    // 16 warps, 4 per SMSP
static constexpr int KT     = 16;     // k-tile for weight staging

// smem layout (floats)
static constexpr int OFF_Y1 = 0;          // 64x512 = 32768 (stage-1 inputs / y1 / fused)
static constexpr int OFF_ND = 32768;      // 64x256 = 16384 (nodes, later y2)
static constexpr int OFF_W  = 49152;      // 2 x 16x256 = 8192 (W double buffer)
static constexpr int OFF_S  = 57344;      // 64 scores
static constexpr int OFF_WT = 57408;      // 64 softmax weights
static constexpr int SMEM_FLOATS = 57472;
static constexpr int SMEM_BYTES  = SMEM_FLOATS * 4;   // 229,888 B

// cooperative load of a 16 x 256 weight tile (as float4s), 512 threads -------
__device__ __forceinline__ void ldgW(float4* pref, const float* __restrict__ gW,
                                     int ldw, int n0, int k0) {
    const int tid = threadIdx.x;
#pragma unroll
    for (int j = 0; j < 2; j++) {
        int f  = tid + (j << 9);          // 0..1023
        int kk = f >> 6;                  // 0..15
        int n  = (f & 63) << 2;           // 0..252
        pref[j] = *(const float4*)(gW + (size_t)(k0 + kk) * ldw + n0 + n);
    }
}
__device__ __forceinline__ void stsW(float* sW, const float4* pref) {
    const int tid = threadIdx.x;
#pragma unroll
    for (int j = 0; j < 2; j++) {
        int f  = tid + (j << 9);
        int kk = f >> 6;
        int n  = (f & 63) << 2;
        *(float4*)(sW + kk * 256 + n) = pref[j];
    }
}

// One GEMM stage: Y[r, n0..n0+256) = act( X[r,:] @ W[:, n0..n0+256) + b )
// 16 warps x TM rows; 32 threads x 8 cols = 256 output cols.
template <int TM, bool RELU>
__device__ __forceinline__ void gemm_tile(
    const float* __restrict__ sX, int ldx, int K,
    const float* __restrict__ gW, int ldw, int n0,
    const float* __restrict__ gB,
    float* __restrict__ Y, int ldy, int rowStride, int rowBase,
    float* __restrict__ sW)
{
    const int tid  = threadIdx.x;
    const int ty   = tid >> 5;
    const int tx   = tid & 31;
    const int rb   = ty * TM;
    const int ncol = tx << 3;             // 8 cols per thread

    float4 bb0 = *(const float4*)(gB + n0 + ncol);
    float4 bb1 = *(const float4*)(gB + n0 + ncol + 4);
    u64 acc[TM][4];
    {
        u64 b0 = pack2(bb0.x, bb0.y), b1 = pack2(bb0.z, bb0.w);
        u64 b2 = pack2(bb1.x, bb1.y), b3 = pack2(bb1.z, bb1.w);
#pragma unroll
        for (int i = 0; i < TM; i++) { acc[i][0]=b0; acc[i][1]=b1; acc[i][2]=b2; acc[i][3]=b3; }
    }

    const int NT = K >> 4;
    float4 pref[2];
    ldgW(pref, gW, ldw, n0, 0);
    stsW(sW, pref);
    if (NT > 1) ldgW(pref, gW, ldw, n0, KT);
    __syncthreads();

    for (int kt = 0; kt < NT; kt++) {
        const float* sWc = sW + ((kt & 1) ? 4096 : 0);
        const float* sXk = sX + (kt << 4);
#pragma unroll
        for (int kk = 0; kk < KT; kk += 4) {
            float4 xv[TM];
#pragma unroll
            for (int i = 0; i < TM; i++)
                xv[i] = *(const float4*)(sXk + (rb + i) * ldx + kk);
#pragma unroll
            for (int dk = 0; dk < 4; dk++) {
                const float* wr = sWc + ((kk + dk) << 8) + ncol;
                ulonglong2 wA = *(const ulonglong2*)(wr);
                ulonglong2 wB = *(const ulonglong2*)(wr + 4);
#pragma unroll
                for (int i = 0; i < TM; i++) {
                    float xs = (dk == 0) ? xv[i].x : (dk == 1) ? xv[i].y
                             : (dk == 2) ? xv[i].z : xv[i].w;
                    u64 xb = pack2(xs, xs);
                    acc[i][0] = fma2(xb, wA.x, acc[i][0]);
                    acc[i][1] = fma2(xb, wA.y, acc[i][1]);
                    acc[i][2] = fma2(xb, wB.x, acc[i][2]);
                    acc[i][3] = fma2(xb, wB.y, acc[i][3]);
                }
            }
        }
        if (kt + 1 < NT) {
            stsW(sW + (((kt + 1) & 1) ? 4096 : 0), pref);
            if (kt + 2 < NT) ldgW(pref, gW, ldw, n0, (kt + 2) << 4);
        }
        __syncthreads();
    }

#pragma unroll
    for (int i = 0; i < TM; i++) {
        int row = rowBase + (rb + i) * rowStride;
        float2 p0 = unpk(acc[i][0]), p1 = unpk(acc[i][1]);
        float2 p2 = unpk(acc[i][2]), p3 = unpk(acc[i][3]);
        if (RELU) {
            p0.x = fmaxf(p0.x, 0.f); p0.y = fmaxf(p0.y, 0.f);
            p1.x = fmaxf(p1.x, 0.f); p1.y = fmaxf(p1.y, 0.f);
            p2.x = fmaxf(p2.x, 0.f); p2.y = fmaxf(p2.y, 0.f);
            p3.x = fmaxf(p3.x, 0.f); p3.y = fmaxf(p3.y, 0.f);
        }
        float4 o0 = make_float4(p0.x, p0.y, p1.x, p1.y);
        float4 o1 = make_float4(p2.x, p2.y, p3.x, p3.y);
        *(float4*)(Y + (size_t)row * ldy + n0 + ncol)     = o0;
        *(float4*)(Y + (size_t)row * ldy + n0 + ncol + 4) = o1;
    }
}

// ---------------------------------------------------------------------------
__global__ void __launch_bounds__(NTHR, 1)
fused_main(const float* __restrict__ audio, const float* __restrict__ text,
           const float* __restrict__ W_pa, const float* __restrict__ b_pa,
           const float* __restrict__ W_pt, const float* __restrict__ b_pt,
           const float* __restrict__ W_g1, const float* __restrict__ b_g1,
           const float* __restrict__ W_g2, const float* __restrict__ b_g2,
           const float* __restrict__ W_af, const float* __restrict__ b_af,
           const float* __restrict__ W_fc, const float* __restrict__ b_fc,
           float* __restrict__ out)
{
    extern __shared__ float smem[];
    float* sY1 = smem + OFF_Y1;
    float* sND = smem + OFF_ND;
    float* sW  = smem + OFF_W;
    float* sS  = smem + OFF_S;
    float* sWt = smem + OFF_WT;

    const int tid = threadIdx.x;
    const int b0  = blockIdx.x * MB;

    // stage 0: stage input tiles (audio -> sY1[0:8192), text -> sY1[8192:16384))
    {
        const float4* gA = (const float4*)(audio + (size_t)b0 * H);
        const float4* gT = (const float4*)(text  + (size_t)b0 * H);
        float4* sA = (float4*)sY1;
        float4* sT = (float4*)(sY1 + 8192);
#pragma unroll
        for (int j = 0; j < 4; j++) { int f = tid + (j << 9); sA[f] = gA[f]; sT[f] = gT[f]; }
    }
    // (gemm prologue __syncthreads orders the stores above before any read)

    // stage 1: projections -> interleaved node rows in sND (32 rows each)
    gemm_tile<2, true >(sY1,        256, 256, W_pa, 256, 0,   b_pa, sND, 256, 2, 0, sW);
    gemm_tile<2, true >(sY1 + 8192, 256, 256, W_pt, 256, 0,   b_pt, sND, 256, 2, 1, sW);
    // stage 2: GAT1 identity path, N=512 in two 256-col chunks -> sY1 (64 rows)
    gemm_tile<4, true >(sND, 256, 256, W_g1, 512, 0,   b_g1, sY1, 512, 1, 0, sW);
    gemm_tile<4, true >(sND, 256, 256, W_g1, 512, 256, b_g1, sY1, 512, 1, 0, sW);
    // stage 3: GAT2 identity path (no relu) -> sND (y2, 64 rows)
    gemm_tile<4, false>(sY1, 512, 512, W_g2, 256, 0,   b_g2, sND, 256, 1, 0, sW);
    __syncthreads();

    // stage 4: attention scores s[r] = y2[r] . W_af + b_af (16 warps x 4 rows)
    {
        const int wid = tid >> 5, lane = tid & 31;
#pragma unroll
        for (int rr = 0; rr < 4; rr++) {
            int r = wid * 4 + rr;
            const float* yr = sND + r * 256;
            float p = 0.f;
#pragma unroll
            for (int j = 0; j < 8; j++) p += yr[lane + (j << 5)] * W_af[lane + (j << 5)];
#pragma unroll
            for (int o = 16; o; o >>= 1) p += __shfl_xor_sync(0xffffffffu, p, o);
            if (lane == 0) sS[r] = p + b_af[0];
        }
    }
    __syncthreads();
    if (tid < MB) {
        float s0 = sS[2 * tid], s1 = sS[2 * tid + 1];
        float mx = fmaxf(s0, s1);
        float e0 = expf(s0 - mx), e1 = expf(s1 - mx);
        float inv = 1.f / (e0 + e1);
        sWt[2 * tid]     = e0 * inv;
        sWt[2 * tid + 1] = e1 * inv;
    }
    __syncthreads();

    // fuse: fused[m] = wa*y2[2m] + wt*y2[2m+1]  -> sY1 rows m (stride 256)
#pragma unroll
    for (int j = 0; j < 4; j++) {
        int f  = tid + (j << 9);          // float4 index, 0..2047
        int m  = f >> 6;                  // 64 float4 per row
        int n4 = f & 63;
        float wa = sWt[2 * m], wt = sWt[2 * m + 1];
        float4 va = ((const float4*)(sND + (2 * m) * 256))[n4];
        float4 vt = ((const float4*)(sND + (2 * m + 1) * 256))[n4];
        float4 o  = make_float4(wa * va.x + wt * vt.x, wa * va.y + wt * vt.y,
                                wa * va.z + wt * vt.z, wa * va.w + wt * vt.w);
        ((float4*)(sY1 + m * 256))[n4] = o;
    }
    // stage 5: output projection (gemm prologue sync covers the stores above)
    gemm_tile<2, false>(sY1, 256, 256, W_fc, 256, 0, b_fc,
                        out + (size_t)b0 * H, 256, 1, 0, sW);
}

// ---------------------------------------------------------------------------
// Batch 0 fixup: full 2x2 GAT attention for nodes {0,1}; overwrites out[0].
// Parallel GEMV: split-k x float4-over-N, all 256 threads busy, MLP >= 8.
// ---------------------------------------------------------------------------
__device__ __forceinline__ float lrelu(float x) { return x > 0.f ? x : 0.2f * x; }

// x: smem [K]; W: global row-major [K x N]; out: smem [N]. 256 threads.
template <bool RELU, bool BIAS>
__device__ __forceinline__ void gemv_fix(
    const float* __restrict__ xs, const float* __restrict__ W,
    int N, int K, const float* __restrict__ gB,
    float* __restrict__ out, float4* __restrict__ red)
{
    const int tid = threadIdx.x;
    const int N4  = N >> 2;               // output groups of 4
    const int S   = 256 / N4;             // k-splits (4 for N=256, 2 for N=512)
    const int g   = tid & (N4 - 1);
    const int s   = tid / N4;
    const int kps = K / S;

    float4 acc = make_float4(0.f, 0.f, 0.f, 0.f);
    const float* Wp = W + (size_t)(s * kps) * N + (g << 2);
    const float* xp = xs + s * kps;
#pragma unroll 8
    for (int k = 0; k < kps; k++) {
        float  xv = xp[k];
        float4 w  = *(const float4*)(Wp + (size_t)k * N);
        acc.x += xv * w.x; acc.y += xv * w.y;
        acc.z += xv * w.z; acc.w += xv * w.w;
    }
    red[tid] = acc;
    __syncthreads();
    if (s == 0) {
        for (int t = 1; t < S; t++) {
            float4 o = red[t * N4 + g];
            acc.x += o.x; acc.y += o.y; acc.z += o.z; acc.w += o.w;
        }
        if (BIAS) {
            float4 b = *(const float4*)(gB + (g << 2));
            acc.x += b.x; acc.y += b.y; acc.z += b.z; acc.w += b.w;
        }
        if (RELU) {
            acc.x = fmaxf(acc.x, 0.f); acc.y = fmaxf(acc.y, 0.f);
            acc.z = fmaxf(acc.z, 0.f); acc.w = fmaxf(acc.w, 0.f);
        }
        ((float4*)out)[g] = acc;
    }
    __syncthreads();
}

__global__ void fix_batch0(
    const float* __restrict__ audio, const float* __restrict__ text,
    const float* __restrict__ W_pa, const float* __restrict__ b_pa,
    const float* __restrict__ W_pt, const float* __restrict__ b_pt,
    const float* __restrict__ W_g1, const float* __restrict__ as1,
    const float* __restrict__ ad1, const float* __restrict__ b_g1,
    const float* __restrict__ W_g2, const float* __restrict__ as2,
    const float* __restrict__ ad2, const float* __restrict__ b_g2,
    const float* __restrict__ W_af, const float* __restrict__ b_af,
    const float* __restrict__ W_fc, const float* __restrict__ b_fc,
    float* __restrict__ out)
{
    __shared__ float a0[256], t0[256], x0[256], x1[256];
    __shared__ float xs1[2][512], y1[2][512];
    __shared__ float xs2[2][256], y2[2][256];
    __shared__ float obuf[256], fused[256];
    __shared__ float sc[16];
    __shared__ float alpha1[2][2][2];   // [t][s][h]
    __shared__ float alpha2[2][2];      // [t][s]
    __shared__ float fw[2];
    __shared__ float4 red[256];         // gemv reduction scratch

    const int tid = threadIdx.x;
    const int wid = tid >> 5, lane = tid & 31;

    a0[tid] = audio[tid]; t0[tid] = text[tid];
    __syncthreads();

    // projections
    gemv_fix<true,  true >(a0, W_pa, 256, 256, b_pa, x0, red);
    gemv_fix<true,  true >(t0, W_pt, 256, 256, b_pt, x1, red);

    // GAT1 projections: xs1[r] = x_r @ W_g1 (no bias yet)
    gemv_fix<false, false>(x0, W_g1, 512, 256, nullptr, xs1[0], red);
    gemv_fix<false, false>(x1, W_g1, 512, 256, nullptr, xs1[1], red);

    // e_src1/e_dst1 : 8 warp reductions. wid: r=bit0, h=bit1, dst=bit2
    if (wid < 8) {
        int r = wid & 1, h = (wid >> 1) & 1, isdst = wid >> 2;
        const float* av = isdst ? ad1 : as1;
        float p = 0.f;
        for (int c = lane; c < 256; c += 32) p += xs1[r][h * 256 + c] * av[h * 256 + c];
#pragma unroll
        for (int o = 16; o; o >>= 1) p += __shfl_xor_sync(0xffffffffu, p, o);
        if (lane == 0) sc[wid] = p;     // sc[(h<<1)|r]=e_src, sc[4+(h<<1)|r]=e_dst
    }
    __syncthreads();
    if (tid == 0) {
        for (int t = 0; t < 2; t++)
            for (int h = 0; h < 2; h++) {
                float l0 = lrelu(sc[(h << 1) | 0] + sc[4 + ((h << 1) | t)]);
                float l1 = lrelu(sc[(h << 1) | 1] + sc[4 + ((h << 1) | t)]);
                float mx = fmaxf(l0, l1);
                float e0 = expf(l0 - mx), e1 = expf(l1 - mx);
                float inv = 1.f / (e0 + e1);
                alpha1[t][0][h] = e0 * inv;
                alpha1[t][1][h] = e1 * inv;
            }
    }
    __syncthreads();
    // y1 = relu(agg + b_g1)
    for (int idx = tid; idx < 1024; idx += 256) {
        int t = idx >> 9, j = idx & 511, h = j >> 8;
        float v = alpha1[t][0][h] * xs1[0][j] + alpha1[t][1][h] * xs1[1][j] + b_g1[j];
        y1[t][j] = fmaxf(v, 0.f);
    }
    __syncthreads();

    // GAT2 projections
    gemv_fix<false, false>(y1[0], W_g2, 256, 512, nullptr, xs2[0], red);
    gemv_fix<false, false>(y1[1], W_g2, 256, 512, nullptr, xs2[1], red);

    if (wid < 4) {
        int r = wid & 1, isdst = wid >> 1;
        const float* av = isdst ? ad2 : as2;
        float p = 0.f;
        for (int c = lane; c < 256; c += 32) p += xs2[r][c] * av[c];
#pragma unroll
        for (int o = 16; o; o >>= 1) p += __shfl_xor_sync(0xffffffffu, p, o);
        if (lane == 0) sc[8 + wid] = p;  // sc[8+r]=e_src2, sc[10+r]=e_dst2
    }
    __syncthreads();
    if (tid == 0) {
        for (int t = 0; t < 2; t++) {
            float l0 = lrelu(sc[8 + 0] + sc[10 + t]);
            float l1 = lrelu(sc[8 + 1] + sc[10 + t]);
            float mx = fmaxf(l0, l1);
            float e0 = expf(l0 - mx), e1 = expf(l1 - mx);
            float inv = 1.f / (e0 + e1);
            alpha2[t][0] = e0 * inv; alpha2[t][1] = e1 * inv;
        }
    }
    __syncthreads();
    // y2 (no relu)
    for (int idx = tid; idx < 512; idx += 256) {
        int t = idx >> 8, j = idx & 255;
        y2[t][j] = alpha2[t][0] * xs2[0][j] + alpha2[t][1] * xs2[1][j] + b_g2[j];
    }
    __syncthreads();
    if (wid < 2) {
        float p = 0.f;
        for (int c = lane; c < 256; c += 32) p += y2[wid][c] * W_af[c];
#pragma unroll
        for (int o = 16; o; o >>= 1) p += __shfl_xor_sync(0xffffffffu, p, o);
        if (lane == 0) sc[12 + wid] = p + b_af[0];
    }
    __syncthreads();
    if (tid == 0) {
        float s0 = sc[12], s1 = sc[13];
        float mx = fmaxf(s0, s1);
        float e0 = expf(s0 - mx), e1 = expf(s1 - mx);
        float inv = 1.f / (e0 + e1);
        fw[0] = e0 * inv; fw[1] = e1 * inv;
    }
    __syncthreads();
    fused[tid] = fw[0] * y2[0][tid] + fw[1] * y2[1][tid];
    __syncthreads();

    // final projection + store
    gemv_fix<false, true >(fused, W_fc, 256, 256, b_fc, obuf, red);
    out[tid] = obuf[tid];
}

// ---------------------------------------------------------------------------
extern "C" void kernel_launch(void* const* d_in, const int* in_sizes, int n_in,
                              void* d_out, int out_size)
{
    const float* audio = (const float*)d_in[0];
    const float* text  = (const float*)d_in[1];
    const float* W_pa  = (const float*)d_in[2];
    const float* b_pa  = (const float*)d_in[3];
    const float* W_pt  = (const float*)d_in[4];
    const float* b_pt  = (const float*)d_in[5];
    const float* W_g1  = (const float*)d_in[6];
    const float* as1   = (const float*)d_in[7];
    const float* ad1   = (const float*)d_in[8];
    const float* b_g1  = (const float*)d_in[9];
    const float* W_g2  = (const float*)d_in[10];
    const float* as2   = (const float*)d_in[11];
    const float* ad2   = (const float*)d_in[12];
    const float* b_g2  = (const float*)d_in[13];
    const float* W_af  = (const float*)d_in[14];
    const float* b_af  = (const float*)d_in[15];
    const float* W_fc  = (const float*)d_in[16];
    const float* b_fc  = (const float*)d_in[17];
    float* out = (float*)d_out;

    const int batch = in_sizes[0] / H;           // 65536
    const int grid  = batch / MB;                // 2048

    cudaFuncSetAttribute(fused_main, cudaFuncAttributeMaxDynamicSharedMemorySize,
                         SMEM_BYTES);

    fused_main<<<grid, NTHR, SMEM_BYTES>>>(
        audio, text, W_pa, b_pa, W_pt, b_pt, W_g1, b_g1, W_g2, b_g2,
        W_af, b_af, W_fc, b_fc, out);

    fix_batch0<<<1, 256>>>(
        audio, text, W_pa, b_pa, W_pt, b_pt, W_g1, as1, ad1, b_g1,
        W_g2, as2, ad2, b_g2, W_af, b_af, W_fc, b_fc, out);
}

// round 7
// speedup vs baseline: 1.7884x; 1.7884x over previous
#include <cuda_runtime.h>
#include <cstdint>
#include <cstdio>

// ---------------------------------------------------------------------------
// GraphFusionLayerAtt: fully-fused fp32 pipeline (f32x2 packed FMA).
//   Identity GAT path for all batch elements; block 0 additionally recomputes
//   the true 2x2 GAT attention for nodes {0,1} inline and overwrites out[0].
// ---------------------------------------------------------------------------

typedef unsigned long long u64;

__device__ __forceinline__ u64 pack2(float x, float y) {
    u64 r; asm("mov.b64 %0, {%1, %2};" : "=l"(r) : "f"(x), "f"(y)); return r;
}
__device__ __forceinline__ u64 fma2(u64 a, u64 b, u64 c) {
    u64 d; asm("fma.rn.f32x2 %0, %1, %2, %3;" : "=l"(d) : "l"(a), "l"(b), "l"(c)); return d;
}
__device__ __forceinline__ float2 unpk(u64 v) {
    float2 f; asm("mov.b64 {%0, %1}, %2;" : "=f"(f.x), "=f"(f.y) : "l"(v)); return f;
}

static constexpr int H      = 256;
static constexpr int MB     = 32;     // batch elements per CTA
static constexpr int NTHR   = 256;    // 8 warps, 2 per SMSP
static constexpr int KT     = 16;     // k-tile for weight staging

// smem layout (floats)
static constexpr int OFF_Y1 = 0;          // 64x512 = 32768 (inputs+dualW / y1 / fused)
static constexpr int OFF_ND = 32768;      // 64x256 = 16384 (nodes, later y2, fixup scratch)
static constexpr int OFF_W  = 49152;      // 2 x 16x256 = 8192 (W double buffer)
static constexpr int OFF_S  = 57344;      // 64 scores
static constexpr int OFF_WT = 57408;      // 64 softmax weights
static constexpr int SMEM_FLOATS = 57472;
static constexpr int SMEM_BYTES  = SMEM_FLOATS * 4;   // 229,888 B

// ---------------------------------------------------------------------------
// cooperative load of a 16 x 256 weight tile (as float4s), 256 threads
__device__ __forceinline__ void ldgW(float4* pref, const float* __restrict__ gW,
                                     int ldw, int n0, int k0) {
    const int tid = threadIdx.x;
#pragma unroll
    for (int j = 0; j < 4; j++) {
        int f  = tid + (j << 8);          // 0..1023
        int kk = f >> 6;                  // 0..15
        int n  = (f & 63) << 2;           // 0..252
        pref[j] = *(const float4*)(gW + (size_t)(k0 + kk) * ldw + n0 + n);
    }
}
__device__ __forceinline__ void stsW(float* sW, const float4* pref) {
    const int tid = threadIdx.x;
#pragma unroll
    for (int j = 0; j < 4; j++) {
        int f = tid + (j << 8);
        ((float4*)sW)[f] = pref[j];       // linear layout == kk*256 + n
    }
}
// dual-tile variant: loads 16x256 tiles of BOTH Wa and Wb (8192 floats)
__device__ __forceinline__ void ldgW_dual(float4* pref, const float* __restrict__ gWa,
                                          const float* __restrict__ gWb, int k0) {
    const int tid = threadIdx.x;
#pragma unroll
    for (int j = 0; j < 8; j++) {
        int f    = tid + (j << 8);        // 0..2047
        int half = f >> 10;
        int f2   = f & 1023;
        int kk   = f2 >> 6;
        int n    = (f2 & 63) << 2;
        const float* W = half ? gWb : gWa;
        pref[j] = *(const float4*)(W + (size_t)(k0 + kk) * 256 + n);
    }
}
__device__ __forceinline__ void stsW_dual(float* buf, const float4* pref) {
    const int tid = threadIdx.x;
#pragma unroll
    for (int j = 0; j < 8; j++) {
        int f = tid + (j << 8);
        ((float4*)buf)[f] = pref[j];      // [0:4096)=Wa tile, [4096:8192)=Wb tile
    }
}

// ---------------------------------------------------------------------------
// One GEMM stage: Y[r, n0..n0+256) = act( X[r,:] @ W[:, n0..n0+256) + b )
// 8 warps x TM rows; 32 lanes x 8 cols = 256 output cols. TM=8 keeps the
// smem crossbar below 128 B/cyc (weight reload cost 512/TM B per fma2-cyc).
template <int TM, bool RELU>
__device__ __forceinline__ void gemm_tile(
    const float* __restrict__ sX, int ldx, int K,
    const float* __restrict__ gW, int ldw, int n0,
    const float* __restrict__ gB,
    float* __restrict__ Y, int ldy, int rowStride, int rowBase,
    float* __restrict__ sW)
{
    const int tid  = threadIdx.x;
    const int ty   = tid >> 5;
    const int tx   = tid & 31;
    const int rb   = ty * TM;
    const int ncol = tx << 3;

    float4 bb0 = *(const float4*)(gB + n0 + ncol);
    float4 bb1 = *(const float4*)(gB + n0 + ncol + 4);
    u64 acc[TM][4];
    {
        u64 b0 = pack2(bb0.x, bb0.y), b1 = pack2(bb0.z, bb0.w);
        u64 b2 = pack2(bb1.x, bb1.y), b3 = pack2(bb1.z, bb1.w);
#pragma unroll
        for (int i = 0; i < TM; i++) { acc[i][0]=b0; acc[i][1]=b1; acc[i][2]=b2; acc[i][3]=b3; }
    }

    const int NT = K >> 4;
    float4 pref[4];
    ldgW(pref, gW, ldw, n0, 0);
    stsW(sW, pref);
    if (NT > 1) ldgW(pref, gW, ldw, n0, KT);
    __syncthreads();

    for (int kt = 0; kt < NT; kt++) {
        const float* sWc = sW + ((kt & 1) ? 4096 : 0);
        const float* sXk = sX + (kt << 4);
#pragma unroll
        for (int kk = 0; kk < KT; kk += 4) {
            float4 xv[TM];
#pragma unroll
            for (int i = 0; i < TM; i++)
                xv[i] = *(const float4*)(sXk + (rb + i) * ldx + kk);
#pragma unroll
            for (int dk = 0; dk < 4; dk++) {
                const float* wr = sWc + ((kk + dk) << 8) + ncol;
                ulonglong2 wA = *(const ulonglong2*)(wr);
                ulonglong2 wB = *(const ulonglong2*)(wr + 4);
#pragma unroll
                for (int i = 0; i < TM; i++) {
                    float xs = (dk == 0) ? xv[i].x : (dk == 1) ? xv[i].y
                             : (dk == 2) ? xv[i].z : xv[i].w;
                    u64 xb = pack2(xs, xs);
                    acc[i][0] = fma2(xb, wA.x, acc[i][0]);
                    acc[i][1] = fma2(xb, wA.y, acc[i][1]);
                    acc[i][2] = fma2(xb, wB.x, acc[i][2]);
                    acc[i][3] = fma2(xb, wB.y, acc[i][3]);
                }
            }
        }
        if (kt + 1 < NT) {
            stsW(sW + (((kt + 1) & 1) ? 4096 : 0), pref);
            if (kt + 2 < NT) ldgW(pref, gW, ldw, n0, (kt + 2) << 4);
        }
        __syncthreads();
    }

#pragma unroll
    for (int i = 0; i < TM; i++) {
        int row = rowBase + (rb + i) * rowStride;
        float2 p0 = unpk(acc[i][0]), p1 = unpk(acc[i][1]);
        float2 p2 = unpk(acc[i][2]), p3 = unpk(acc[i][3]);
        if (RELU) {
            p0.x = fmaxf(p0.x, 0.f); p0.y = fmaxf(p0.y, 0.f);
            p1.x = fmaxf(p1.x, 0.f); p1.y = fmaxf(p1.y, 0.f);
            p2.x = fmaxf(p2.x, 0.f); p2.y = fmaxf(p2.y, 0.f);
            p3.x = fmaxf(p3.x, 0.f); p3.y = fmaxf(p3.y, 0.f);
        }
        *(float4*)(Y + (size_t)row * ldy + ncol + n0)     = make_float4(p0.x, p0.y, p1.x, p1.y);
        *(float4*)(Y + (size_t)row * ldy + ncol + n0 + 4) = make_float4(p2.x, p2.y, p3.x, p3.y);
    }
}

// ---------------------------------------------------------------------------
// Stage-1 dual-weight GEMM: 64 rows (0-31 audio via W_pa, 32-63 text via W_pt),
// TM=8, relu, output interleaved into sND (audio m -> row 2m, text m -> 2m+1).
// Weight tiles double-buffered in sWbig (2 x 8192 floats, upper half of sY1).
__device__ __forceinline__ void gemm_dual(
    const float* __restrict__ sX,                    // 64 x 256
    const float* __restrict__ gWa, const float* __restrict__ gWb,
    const float* __restrict__ bA,  const float* __restrict__ bB,
    float* __restrict__ Y,                           // sND, ld 256
    float* __restrict__ sWbig)
{
    const int tid  = threadIdx.x;
    const int ty   = tid >> 5;
    const int tx   = tid & 31;
    const int rb   = ty * 8;
    const int ncol = tx << 3;
    const bool sel = rb >= 32;                       // warps 4-7: text / W_pt

    const float* gB = sel ? bB : bA;
    float4 bb0 = *(const float4*)(gB + ncol);
    float4 bb1 = *(const float4*)(gB + ncol + 4);
    u64 acc[8][4];
    {
        u64 b0 = pack2(bb0.x, bb0.y), b1 = pack2(bb0.z, bb0.w);
        u64 b2 = pack2(bb1.x, bb1.y), b3 = pack2(bb1.z, bb1.w);
#pragma unroll
        for (int i = 0; i < 8; i++) { acc[i][0]=b0; acc[i][1]=b1; acc[i][2]=b2; acc[i][3]=b3; }
    }

    const int NT = 16;                               // K = 256
    float4 pref[8];
    ldgW_dual(pref, gWa, gWb, 0);
    stsW_dual(sWbig, pref);
    ldgW_dual(pref, gWa, gWb, KT);
    __syncthreads();

    const int wsel = sel ? 4096 : 0;
    for (int kt = 0; kt < NT; kt++) {
        const float* sWc = sWbig + ((kt & 1) ? 8192 : 0) + wsel;
        const float* sXk = sX + (kt << 4);
#pragma unroll
        for (int kk = 0; kk < KT; kk += 4) {
            float4 xv[8];
#pragma unroll
            for (int i = 0; i < 8; i++)
                xv[i] = *(const float4*)(sXk + (rb + i) * 256 + kk);
#pragma unroll
            for (int dk = 0; dk < 4; dk++) {
                const float* wr = sWc + ((kk + dk) << 8) + ncol;
                ulonglong2 wA = *(const ulonglong2*)(wr);
                ulonglong2 wB = *(const ulonglong2*)(wr + 4);
#pragma unroll
                for (int i = 0; i < 8; i++) {
                    float xs = (dk == 0) ? xv[i].x : (dk == 1) ? xv[i].y
                             : (dk == 2) ? xv[i].z : xv[i].w;
                    u64 xb = pack2(xs, xs);
                    acc[i][0] = fma2(xb, wA.x, acc[i][0]);
                    acc[i][1] = fma2(xb, wA.y, acc[i][1]);
                    acc[i][2] = fma2(xb, wB.x, acc[i][2]);
                    acc[i][3] = fma2(xb, wB.y, acc[i][3]);
                }
            }
        }
        if (kt + 1 < NT) {
            stsW_dual(sWbig + (((kt + 1) & 1) ? 8192 : 0), pref);
            if (kt + 2 < NT) ldgW_dual(pref, gWa, gWb, (kt + 2) << 4);
        }
        __syncthreads();
    }

    // epilogue: relu + interleave
    const int rowBase = sel ? (((rb - 32) << 1) | 1) : (rb << 1);
#pragma unroll
    for (int i = 0; i < 8; i++) {
        int row = rowBase + (i << 1);
        float2 p0 = unpk(acc[i][0]), p1 = unpk(acc[i][1]);
        float2 p2 = unpk(acc[i][2]), p3 = unpk(acc[i][3]);
        p0.x = fmaxf(p0.x, 0.f); p0.y = fmaxf(p0.y, 0.f);
        p1.x = fmaxf(p1.x, 0.f); p1.y = fmaxf(p1.y, 0.f);
        p2.x = fmaxf(p2.x, 0.f); p2.y = fmaxf(p2.y, 0.f);
        p3.x = fmaxf(p3.x, 0.f); p3.y = fmaxf(p3.y, 0.f);
        *(float4*)(Y + row * 256 + ncol)     = make_float4(p0.x, p0.y, p1.x, p1.y);
        *(float4*)(Y + row * 256 + ncol + 4) = make_float4(p2.x, p2.y, p3.x, p3.y);
    }
}

// ---------------------------------------------------------------------------
// Batch-0 fixup helpers (run by block 0 only, 256 threads, smem scratch)
// ---------------------------------------------------------------------------
__device__ __forceinline__ float lrelu(float x) { return x > 0.f ? x : 0.2f * x; }

// x: smem [K]; W: global row-major [K x N]; out: smem [N]. 256 threads.
template <bool RELU, bool BIAS>
__device__ __forceinline__ void gemv_fix(
    const float* __restrict__ xs, const float* __restrict__ W,
    int N, int K, const float* __restrict__ gB,
    float* __restrict__ out, float4* __restrict__ red)
{
    const int tid = threadIdx.x;
    const int N4  = N >> 2;
    const int S   = 256 / N4;             // k-splits
    const int g   = tid & (N4 - 1);
    const int s   = tid / N4;
    const int kps = K / S;

    float4 acc = make_float4(0.f, 0.f, 0.f, 0.f);
    const float* Wp = W + (size_t)(s * kps) * N + (g << 2);
    const float* xp = xs + s * kps;
#pragma unroll 8
    for (int k = 0; k < kps; k++) {
        float  xv = xp[k];
        float4 w  = *(const float4*)(Wp + (size_t)k * N);
        acc.x += xv * w.x; acc.y += xv * w.y;
        acc.z += xv * w.z; acc.w += xv * w.w;
    }
    red[tid] = acc;
    __syncthreads();
    if (s == 0) {
        for (int t = 1; t < S; t++) {
            float4 o = red[t * N4 + g];
            acc.x += o.x; acc.y += o.y; acc.z += o.z; acc.w += o.w;
        }
        if (BIAS) {
            float4 b = *(const float4*)(gB + (g << 2));
            acc.x += b.x; acc.y += b.y; acc.z += b.z; acc.w += b.w;
        }
        if (RELU) {
            acc.x = fmaxf(acc.x, 0.f); acc.y = fmaxf(acc.y, 0.f);
            acc.z = fmaxf(acc.z, 0.f); acc.w = fmaxf(acc.w, 0.f);
        }
        ((float4*)out)[g] = acc;
    }
    __syncthreads();
}

__device__ void fixup_b0(
    float* __restrict__ scr,              // >= 5664 floats of smem scratch
    const float* __restrict__ audio, const float* __restrict__ text,
    const float* __restrict__ W_pa, const float* __restrict__ b_pa,
    const float* __restrict__ W_pt, const float* __restrict__ b_pt,
    const float* __restrict__ W_g1, const float* __restrict__ as1,
    const float* __restrict__ ad1, const float* __restrict__ b_g1,
    const float* __restrict__ W_g2, const float* __restrict__ as2,
    const float* __restrict__ ad2, const float* __restrict__ b_g2,
    const float* __restrict__ W_af, const float* __restrict__ b_af,
    const float* __restrict__ W_fc, const float* __restrict__ b_fc,
    float* __restrict__ out)
{
    float* a0    = scr;          // 256
    float* t0    = scr + 256;
    float* x0    = scr + 512;
    float* x1    = scr + 768;
    float* xs1   = scr + 1024;   // 2 x 512
    float* y1    = scr + 2048;   // 2 x 512
    float* xs2   = scr + 3072;   // 2 x 256
    float* y2    = scr + 3584;   // 2 x 256
    float* fused = scr + 4096;   // 256
    float* obuf  = scr + 4352;   // 256
    float* sc    = scr + 4608;   // 16
    float* al1   = scr + 4624;   // 8: [t][s][h]
    float* al2   = scr + 4632;   // 4: [t][s]
    float* fw    = scr + 4636;   // 2
    float4* red  = (float4*)(scr + 4640);  // 256 float4

    const int tid = threadIdx.x;
    const int wid = tid >> 5, lane = tid & 31;

    a0[tid] = audio[tid]; t0[tid] = text[tid];
    __syncthreads();

    gemv_fix<true,  true >(a0, W_pa, 256, 256, b_pa, x0, red);
    gemv_fix<true,  true >(t0, W_pt, 256, 256, b_pt, x1, red);
    gemv_fix<false, false>(x0, W_g1, 512, 256, nullptr, xs1,       red);
    gemv_fix<false, false>(x1, W_g1, 512, 256, nullptr, xs1 + 512, red);

    // e_src1/e_dst1: 8 warp reductions. wid: r=bit0, h=bit1, dst=bit2
    {
        int r = wid & 1, h = (wid >> 1) & 1, isdst = wid >> 2;
        const float* av = isdst ? ad1 : as1;
        float p = 0.f;
        for (int c = lane; c < 256; c += 32) p += xs1[r * 512 + h * 256 + c] * av[h * 256 + c];
#pragma unroll
        for (int o = 16; o; o >>= 1) p += __shfl_xor_sync(0xffffffffu, p, o);
        if (lane == 0) sc[wid] = p;
    }
    __syncthreads();
    if (tid == 0) {
        for (int t = 0; t < 2; t++)
            for (int h = 0; h < 2; h++) {
                float l0 = lrelu(sc[(h << 1) | 0] + sc[4 + ((h << 1) | t)]);
                float l1 = lrelu(sc[(h << 1) | 1] + sc[4 + ((h << 1) | t)]);
                float mx = fmaxf(l0, l1);
                float e0 = expf(l0 - mx), e1 = expf(l1 - mx);
                float inv = 1.f / (e0 + e1);
                al1[(t * 2 + 0) * 2 + h] = e0 * inv;
                al1[(t * 2 + 1) * 2 + h] = e1 * inv;
            }
    }
    __syncthreads();
    for (int idx = tid; idx < 1024; idx += 256) {
        int t = idx >> 9, j = idx & 511, h = j >> 8;
        float v = al1[(t * 2 + 0) * 2 + h] * xs1[j] + al1[(t * 2 + 1) * 2 + h] * xs1[512 + j] + b_g1[j];
        y1[t * 512 + j] = fmaxf(v, 0.f);
    }
    __syncthreads();

    gemv_fix<false, false>(y1,       W_g2, 256, 512, nullptr, xs2,       red);
    gemv_fix<false, false>(y1 + 512, W_g2, 256, 512, nullptr, xs2 + 256, red);

    if (wid < 4) {
        int r = wid & 1, isdst = wid >> 1;
        const float* av = isdst ? ad2 : as2;
        float p = 0.f;
        for (int c = lane; c < 256; c += 32) p += xs2[r * 256 + c] * av[c];
#pragma unroll
        for (int o = 16; o; o >>= 1) p += __shfl_xor_sync(0xffffffffu, p, o);
        if (lane == 0) sc[8 + wid] = p;
    }
    __syncthreads();
    if (tid == 0) {
        for (int t = 0; t < 2; t++) {
            float l0 = lrelu(sc[8 + 0] + sc[10 + t]);
            float l1 = lrelu(sc[8 + 1] + sc[10 + t]);
            float mx = fmaxf(l0, l1);
            float e0 = expf(l0 - mx), e1 = expf(l1 - mx);
            float inv = 1.f / (e0 + e1);
            al2[t * 2 + 0] = e0 * inv; al2[t * 2 + 1] = e1 * inv;
        }
    }
    __syncthreads();
    for (int idx = tid; idx < 512; idx += 256) {
        int t = idx >> 8, j = idx & 255;
        y2[t * 256 + j] = al2[t * 2 + 0] * xs2[j] + al2[t * 2 + 1] * xs2[256 + j] + b_g2[j];
    }
    __syncthreads();
    if (wid < 2) {
        float p = 0.f;
        for (int c = lane; c < 256; c += 32) p += y2[wid * 256 + c] * W_af[c];
#pragma unroll
        for (int o = 16; o; o >>= 1) p += __shfl_xor_sync(0xffffffffu, p, o);
        if (lane == 0) sc[12 + wid] = p + b_af[0];
    }
    __syncthreads();
    if (tid == 0) {
        float s0 = sc[12], s1 = sc[13];
        float mx = fmaxf(s0, s1);
        float e0 = expf(s0 - mx), e1 = expf(s1 - mx);
        float inv = 1.f / (e0 + e1);
        fw[0] = e0 * inv; fw[1] = e1 * inv;
    }
    __syncthreads();
    fused[tid] = fw[0] * y2[tid] + fw[1] * y2[256 + tid];
    __syncthreads();

    gemv_fix<false, true>(fused, W_fc, 256, 256, b_fc, obuf, red);
    out[tid] = obuf[tid];
}

// ---------------------------------------------------------------------------
__global__ void __launch_bounds__(NTHR, 1)
fused_main(const float* __restrict__ audio, const float* __restrict__ text,
           const float* __restrict__ W_pa, const float* __restrict__ b_pa,
           const float* __restrict__ W_pt, const float* __restrict__ b_pt,
           const float* __restrict__ W_g1, const float* __restrict__ as1,
           const float* __restrict__ ad1, const float* __restrict__ b_g1,
           const float* __restrict__ W_g2, const float* __restrict__ as2,
           const float* __restrict__ ad2, const float* __restrict__ b_g2,
           const float* __restrict__ W_af, const float* __restrict__ b_af,
           const float* __restrict__ W_fc, const float* __restrict__ b_fc,
           float* __restrict__ out)
{
    extern __shared__ float smem[];
    float* sY1 = smem + OFF_Y1;
    float* sND = smem + OFF_ND;
    float* sW  = smem + OFF_W;
    float* sS  = smem + OFF_S;
    float* sWt = smem + OFF_WT;

    const int tid = threadIdx.x;
    const int b0  = blockIdx.x * MB;

    // stage 0: inputs -> sY1 rows 0-31 (audio), rows 32-63 (text)
    {
        const float4* gA = (const float4*)(audio + (size_t)b0 * H);
        const float4* gT = (const float4*)(text  + (size_t)b0 * H);
        float4* sA = (float4*)sY1;
        float4* sT = (float4*)(sY1 + 8192);
#pragma unroll
        for (int j = 0; j < 8; j++) { int f = tid + (j << 8); sA[f] = gA[f]; sT[f] = gT[f]; }
    }
    // (gemm_dual prologue __syncthreads orders the stores above)

    // stage 1: dual-weight projection, 64 rows, TM=8, interleaved -> sND.
    // Weight double-buffer lives in the free upper half of sY1.
    gemm_dual(sY1, W_pa, W_pt, b_pa, b_pt, sND, sY1 + 16384);

    // stage 2: GAT1 identity path, N=512 in two 256-col chunks -> sY1 (64 rows)
    gemm_tile<8, true >(sND, 256, 256, W_g1, 512, 0,   b_g1, sY1, 512, 1, 0, sW);
    gemm_tile<8, true >(sND, 256, 256, W_g1, 512, 256, b_g1, sY1, 512, 1, 0, sW);
    // stage 3: GAT2 identity path (no relu) -> sND (y2, 64 rows)
    gemm_tile<8, false>(sY1, 512, 512, W_g2, 256, 0,   b_g2, sND, 256, 1, 0, sW);
    __syncthreads();

    // stage 4: attention scores s[r] = y2[r] . W_af + b_af (8 warps x 8 rows)
    {
        const int wid = tid >> 5, lane = tid & 31;
#pragma unroll
        for (int rr = 0; rr < 8; rr++) {
            int r = wid * 8 + rr;
            const float* yr = sND + r * 256;
            float p = 0.f;
#pragma unroll
            for (int j = 0; j < 8; j++) p += yr[lane + (j << 5)] * W_af[lane + (j << 5)];
#pragma unroll
            for (int o = 16; o; o >>= 1) p += __shfl_xor_sync(0xffffffffu, p, o);
            if (lane == 0) sS[r] = p + b_af[0];
        }
    }
    __syncthreads();
    if (tid < MB) {
        float s0 = sS[2 * tid], s1 = sS[2 * tid + 1];
        float mx = fmaxf(s0, s1);
        float e0 = expf(s0 - mx), e1 = expf(s1 - mx);
        float inv = 1.f / (e0 + e1);
        sWt[2 * tid]     = e0 * inv;
        sWt[2 * tid + 1] = e1 * inv;
    }
    __syncthreads();

    // fuse: fused[m] = wa*y2[2m] + wt*y2[2m+1]  -> sY1 rows m (stride 256)
#pragma unroll
    for (int j = 0; j < 8; j++) {
        int f  = tid + (j << 8);          // float4 index, 0..2047
        int m  = f >> 6;
        int n4 = f & 63;
        float wa = sWt[2 * m], wt = sWt[2 * m + 1];
        float4 va = ((const float4*)(sND + (2 * m) * 256))[n4];
        float4 vt = ((const float4*)(sND + (2 * m + 1) * 256))[n4];
        ((float4*)(sY1 + m * 256))[n4] =
            make_float4(wa * va.x + wt * vt.x, wa * va.y + wt * vt.y,
                        wa * va.z + wt * vt.z, wa * va.w + wt * vt.w);
    }
    // stage 5: output projection (gemm prologue sync covers the stores above)
    gemm_tile<4, false>(sY1, 256, 256, W_fc, 256, 0, b_fc,
                        out + (size_t)b0 * H, 256, 1, 0, sW);

    // block 0: recompute true GAT attention for batch 0, overwrite out[0].
    // Same block wrote out row 0 in stage 5; __syncthreads orders the stores.
    if (blockIdx.x == 0) {
        __syncthreads();
        fixup_b0(sND, audio, text, W_pa, b_pa, W_pt, b_pt,
                 W_g1, as1, ad1, b_g1, W_g2, as2, ad2, b_g2,
                 W_af, b_af, W_fc, b_fc, out);
    }
}

// ---------------------------------------------------------------------------
extern "C" void kernel_launch(void* const* d_in, const int* in_sizes, int n_in,
                              void* d_out, int out_size)
{
    const float* audio = (const float*)d_in[0];
    const float* text  = (const float*)d_in[1];
    const float* W_pa  = (const float*)d_in[2];
    const float* b_pa  = (const float*)d_in[3];
    const float* W_pt  = (const float*)d_in[4];
    const float* b_pt  = (const float*)d_in[5];
    const float* W_g1  = (const float*)d_in[6];
    const float* as1   = (const float*)d_in[7];
    const float* ad1   = (const float*)d_in[8];
    const float* b_g1  = (const float*)d_in[9];
    const float* W_g2  = (const float*)d_in[10];
    const float* as2   = (const float*)d_in[11];
    const float* ad2   = (const float*)d_in[12];
    const float* b_g2  = (const float*)d_in[13];
    const float* W_af  = (const float*)d_in[14];
    const float* b_af  = (const float*)d_in[15];
    const float* W_fc  = (const float*)d_in[16];
    const float* b_fc  = (const float*)d_in[17];
    float* out = (float*)d_out;

    const int batch = in_sizes[0] / H;           // 65536
    const int grid  = batch / MB;                // 2048

    cudaFuncSetAttribute(fused_main, cudaFuncAttributeMaxDynamicSharedMemorySize,
                         SMEM_BYTES);

    fused_main<<<grid, NTHR, SMEM_BYTES>>>(
        audio, text, W_pa, b_pa, W_pt, b_pt, W_g1, as1, ad1, b_g1,
        W_g2, as2, ad2, b_g2, W_af, b_af, W_fc, b_fc, out);
}

// round 8
// speedup vs baseline: 1.9486x; 1.0896x over previous
#include <cuda_runtime.h>
#include <cstdint>
#include <cstdio>

// ---------------------------------------------------------------------------
// GraphFusionLayerAtt: fully-fused fp32 pipeline (f32x2 packed FMA).
//   Col-split GEMM geometry: 4 row-groups x 2 col-groups, TM=16 rows/warp,
//   4 cols/thread -> halves the (binding) shared-crossbar weight traffic.
//   Identity GAT path for all batch elements; block 0 additionally recomputes
//   the true 2x2 GAT attention for nodes {0,1} inline and overwrites out[0].
// ---------------------------------------------------------------------------

typedef unsigned long long u64;

__device__ __forceinline__ u64 pack2(float x, float y) {
    u64 r; asm("mov.b64 %0, {%1, %2};" : "=l"(r) : "f"(x), "f"(y)); return r;
}
__device__ __forceinline__ u64 fma2(u64 a, u64 b, u64 c) {
    u64 d; asm("fma.rn.f32x2 %0, %1, %2, %3;" : "=l"(d) : "l"(a), "l"(b), "l"(c)); return d;
}
__device__ __forceinline__ float2 unpk(u64 v) {
    float2 f; asm("mov.b64 {%0, %1}, %2;" : "=f"(f.x), "=f"(f.y) : "l"(v)); return f;
}

static constexpr int H      = 256;
static constexpr int MB     = 32;     // batch elements per CTA
static constexpr int NTHR   = 256;    // 8 warps, 2 per SMSP
static constexpr int KT     = 16;     // k-tile for weight staging

// smem layout (floats)
static constexpr int OFF_Y1 = 0;          // 64x512 = 32768 (inputs+dualW / y1 / fused)
static constexpr int OFF_ND = 32768;      // 64x256 = 16384 (nodes, later y2, fixup scratch)
static constexpr int OFF_W  = 49152;      // 2 x 16x256 = 8192 (W double buffer)
static constexpr int OFF_S  = 57344;      // 64 scores
static constexpr int OFF_WT = 57408;      // 64 softmax weights
static constexpr int SMEM_FLOATS = 57472;
static constexpr int SMEM_BYTES  = SMEM_FLOATS * 4;   // 229,888 B

// ---------------------------------------------------------------------------
// cooperative load of a 16 x 256 weight tile (as float4s), 256 threads
__device__ __forceinline__ void ldgW(float4* pref, const float* __restrict__ gW,
                                     int ldw, int n0, int k0) {
    const int tid = threadIdx.x;
#pragma unroll
    for (int j = 0; j < 4; j++) {
        int f  = tid + (j << 8);          // 0..1023
        int kk = f >> 6;                  // 0..15
        int n  = (f & 63) << 2;           // 0..252
        pref[j] = *(const float4*)(gW + (size_t)(k0 + kk) * ldw + n0 + n);
    }
}
__device__ __forceinline__ void stsW(float* sW, const float4* pref) {
    const int tid = threadIdx.x;
#pragma unroll
    for (int j = 0; j < 4; j++) {
        int f = tid + (j << 8);
        ((float4*)sW)[f] = pref[j];       // linear layout == kk*256 + n
    }
}
// dual-tile variant: loads 16x256 tiles of BOTH Wa and Wb (8192 floats)
__device__ __forceinline__ void ldgW_dual(float4* pref, const float* __restrict__ gWa,
                                          const float* __restrict__ gWb, int k0) {
    const int tid = threadIdx.x;
#pragma unroll
    for (int j = 0; j < 8; j++) {
        int f    = tid + (j << 8);        // 0..2047
        int half = f >> 10;
        int f2   = f & 1023;
        int kk   = f2 >> 6;
        int n    = (f2 & 63) << 2;
        const float* W = half ? gWb : gWa;
        pref[j] = *(const float4*)(W + (size_t)(k0 + kk) * 256 + n);
    }
}
__device__ __forceinline__ void stsW_dual(float* buf, const float4* pref) {
    const int tid = threadIdx.x;
#pragma unroll
    for (int j = 0; j < 8; j++) {
        int f = tid + (j << 8);
        ((float4*)buf)[f] = pref[j];      // [0:4096)=Wa tile, [4096:8192)=Wb tile
    }
}

// ---------------------------------------------------------------------------
// Col-split GEMM stage: Y[r, n0..n0+256) = act( X[r,:] @ W[:, n0..n0+256) + b )
// Warp w: row-group = w>>1 (TM rows), col-group = w&1 (128 cols, 4/thread).
// Weight LDS halved vs full-width warps (each tile half read by 4 warps).
template <int TM, bool RELU>
__device__ __forceinline__ void gemm_tile(
    const float* __restrict__ sX, int ldx, int K,
    const float* __restrict__ gW, int ldw, int n0,
    const float* __restrict__ gB,
    float* __restrict__ Y, int ldy, int rowStride, int rowBase,
    float* __restrict__ sW)
{
    const int tid  = threadIdx.x;
    const int warp = tid >> 5;
    const int lane = tid & 31;
    const int rb   = (warp >> 1) * TM;
    const int ncol = ((warp & 1) << 7) | (lane << 2);   // 4 cols per thread

    float4 bb = *(const float4*)(gB + n0 + ncol);
    u64 acc[TM][2];
    {
        u64 b0 = pack2(bb.x, bb.y), b1 = pack2(bb.z, bb.w);
#pragma unroll
        for (int i = 0; i < TM; i++) { acc[i][0] = b0; acc[i][1] = b1; }
    }

    const int NT = K >> 4;
    float4 pref[4];
    ldgW(pref, gW, ldw, n0, 0);
    stsW(sW, pref);
    if (NT > 1) ldgW(pref, gW, ldw, n0, KT);
    __syncthreads();

    for (int kt = 0; kt < NT; kt++) {
        const float* sWc = sW + ((kt & 1) ? 4096 : 0);
        const float* sXk = sX + (kt << 4);
#pragma unroll
        for (int kk = 0; kk < KT; kk += 4) {
            float4 xv[TM];
#pragma unroll
            for (int i = 0; i < TM; i++)
                xv[i] = *(const float4*)(sXk + (rb + i) * ldx + kk);
#pragma unroll
            for (int dk = 0; dk < 4; dk++) {
                ulonglong2 wv = *(const ulonglong2*)(sWc + ((kk + dk) << 8) + ncol);
#pragma unroll
                for (int i = 0; i < TM; i++) {
                    float xs = (dk == 0) ? xv[i].x : (dk == 1) ? xv[i].y
                             : (dk == 2) ? xv[i].z : xv[i].w;
                    u64 xb = pack2(xs, xs);
                    acc[i][0] = fma2(xb, wv.x, acc[i][0]);
                    acc[i][1] = fma2(xb, wv.y, acc[i][1]);
                }
            }
        }
        if (kt + 1 < NT) {
            stsW(sW + (((kt + 1) & 1) ? 4096 : 0), pref);
            if (kt + 2 < NT) ldgW(pref, gW, ldw, n0, (kt + 2) << 4);
        }
        __syncthreads();
    }

#pragma unroll
    for (int i = 0; i < TM; i++) {
        int row = rowBase + (rb + i) * rowStride;
        float2 p0 = unpk(acc[i][0]), p1 = unpk(acc[i][1]);
        if (RELU) {
            p0.x = fmaxf(p0.x, 0.f); p0.y = fmaxf(p0.y, 0.f);
            p1.x = fmaxf(p1.x, 0.f); p1.y = fmaxf(p1.y, 0.f);
        }
        *(float4*)(Y + (size_t)row * ldy + n0 + ncol) = make_float4(p0.x, p0.y, p1.x, p1.y);
    }
}

// ---------------------------------------------------------------------------
// Stage-1 dual-weight GEMM (col-split): rows 0-31 audio (W_pa), 32-63 text
// (W_pt); TM=16, relu, output interleaved into sND (audio m -> row 2m,
// text m -> 2m+1). Weight tiles double-buffered in sWbig (2 x 8192 floats).
__device__ __forceinline__ void gemm_dual(
    const float* __restrict__ sX,                    // 64 x 256
    const float* __restrict__ gWa, const float* __restrict__ gWb,
    const float* __restrict__ bA,  const float* __restrict__ bB,
    float* __restrict__ Y,                           // sND, ld 256
    float* __restrict__ sWbig)
{
    const int tid  = threadIdx.x;
    const int warp = tid >> 5;
    const int lane = tid & 31;
    const int rowg = warp >> 1;
    const int rb   = rowg * 16;
    const int ncol = ((warp & 1) << 7) | (lane << 2);
    const bool sel = rowg >= 2;                      // row-groups 2,3: text / W_pt

    const float* gB = sel ? bB : bA;
    float4 bb = *(const float4*)(gB + ncol);
    u64 acc[16][2];
    {
        u64 b0 = pack2(bb.x, bb.y), b1 = pack2(bb.z, bb.w);
#pragma unroll
        for (int i = 0; i < 16; i++) { acc[i][0] = b0; acc[i][1] = b1; }
    }

    const int NT = 16;                               // K = 256
    float4 pref[8];
    ldgW_dual(pref, gWa, gWb, 0);
    stsW_dual(sWbig, pref);
    ldgW_dual(pref, gWa, gWb, KT);
    __syncthreads();

    const int wsel = sel ? 4096 : 0;
    for (int kt = 0; kt < NT; kt++) {
        const float* sWc = sWbig + ((kt & 1) ? 8192 : 0) + wsel;
        const float* sXk = sX + (kt << 4);
#pragma unroll
        for (int kk = 0; kk < KT; kk += 4) {
            float4 xv[16];
#pragma unroll
            for (int i = 0; i < 16; i++)
                xv[i] = *(const float4*)(sXk + (rb + i) * 256 + kk);
#pragma unroll
            for (int dk = 0; dk < 4; dk++) {
                ulonglong2 wv = *(const ulonglong2*)(sWc + ((kk + dk) << 8) + ncol);
#pragma unroll
                for (int i = 0; i < 16; i++) {
                    float xs = (dk == 0) ? xv[i].x : (dk == 1) ? xv[i].y
                             : (dk == 2) ? xv[i].z : xv[i].w;
                    u64 xb = pack2(xs, xs);
                    acc[i][0] = fma2(xb, wv.x, acc[i][0]);
                    acc[i][1] = fma2(xb, wv.y, acc[i][1]);
                }
            }
        }
        if (kt + 1 < NT) {
            stsW_dual(sWbig + (((kt + 1) & 1) ? 8192 : 0), pref);
            if (kt + 2 < NT) ldgW_dual(pref, gWa, gWb, (kt + 2) << 4);
        }
        __syncthreads();
    }

    // epilogue: relu + interleave (audio row r -> node 2r; text r -> 2(r-32)+1)
    const int rowBase = sel ? (((rb - 32) << 1) | 1) : (rb << 1);
#pragma unroll
    for (int i = 0; i < 16; i++) {
        int row = rowBase + (i << 1);
        float2 p0 = unpk(acc[i][0]), p1 = unpk(acc[i][1]);
        p0.x = fmaxf(p0.x, 0.f); p0.y = fmaxf(p0.y, 0.f);
        p1.x = fmaxf(p1.x, 0.f); p1.y = fmaxf(p1.y, 0.f);
        *(float4*)(Y + row * 256 + ncol) = make_float4(p0.x, p0.y, p1.x, p1.y);
    }
}

// ---------------------------------------------------------------------------
// Batch-0 fixup helpers (run by block 0 only, 256 threads, smem scratch)
// ---------------------------------------------------------------------------
__device__ __forceinline__ float lrelu(float x) { return x > 0.f ? x : 0.2f * x; }

// x: smem [K]; W: global row-major [K x N]; out: smem [N]. 256 threads.
template <bool RELU, bool BIAS>
__device__ __forceinline__ void gemv_fix(
    const float* __restrict__ xs, const float* __restrict__ W,
    int N, int K, const float* __restrict__ gB,
    float* __restrict__ out, float4* __restrict__ red)
{
    const int tid = threadIdx.x;
    const int N4  = N >> 2;
    const int S   = 256 / N4;             // k-splits
    const int g   = tid & (N4 - 1);
    const int s   = tid / N4;
    const int kps = K / S;

    float4 acc = make_float4(0.f, 0.f, 0.f, 0.f);
    const float* Wp = W + (size_t)(s * kps) * N + (g << 2);
    const float* xp = xs + s * kps;
#pragma unroll 8
    for (int k = 0; k < kps; k++) {
        float  xv = xp[k];
        float4 w  = *(const float4*)(Wp + (size_t)k * N);
        acc.x += xv * w.x; acc.y += xv * w.y;
        acc.z += xv * w.z; acc.w += xv * w.w;
    }
    red[tid] = acc;
    __syncthreads();
    if (s == 0) {
        for (int t = 1; t < S; t++) {
            float4 o = red[t * N4 + g];
            acc.x += o.x; acc.y += o.y; acc.z += o.z; acc.w += o.w;
        }
        if (BIAS) {
            float4 b = *(const float4*)(gB + (g << 2));
            acc.x += b.x; acc.y += b.y; acc.z += b.z; acc.w += b.w;
        }
        if (RELU) {
            acc.x = fmaxf(acc.x, 0.f); acc.y = fmaxf(acc.y, 0.f);
            acc.z = fmaxf(acc.z, 0.f); acc.w = fmaxf(acc.w, 0.f);
        }
        ((float4*)out)[g] = acc;
    }
    __syncthreads();
}

__device__ void fixup_b0(
    float* __restrict__ scr,              // >= 5664 floats of smem scratch
    const float* __restrict__ audio, const float* __restrict__ text,
    const float* __restrict__ W_pa, const float* __restrict__ b_pa,
    const float* __restrict__ W_pt, const float* __restrict__ b_pt,
    const float* __restrict__ W_g1, const float* __restrict__ as1,
    const float* __restrict__ ad1, const float* __restrict__ b_g1,
    const float* __restrict__ W_g2, const float* __restrict__ as2,
    const float* __restrict__ ad2, const float* __restrict__ b_g2,
    const float* __restrict__ W_af, const float* __restrict__ b_af,
    const float* __restrict__ W_fc, const float* __restrict__ b_fc,
    float* __restrict__ out)
{
    float* a0    = scr;          // 256
    float* t0    = scr + 256;
    float* x0    = scr + 512;
    float* x1    = scr + 768;
    float* xs1   = scr + 1024;   // 2 x 512
    float* y1    = scr + 2048;   // 2 x 512
    float* xs2   = scr + 3072;   // 2 x 256
    float* y2    = scr + 3584;   // 2 x 256
    float* fused = scr + 4096;   // 256
    float* obuf  = scr + 4352;   // 256
    float* sc    = scr + 4608;   // 16
    float* al1   = scr + 4624;   // 8: [t][s][h]
    float* al2   = scr + 4632;   // 4: [t][s]
    float* fw    = scr + 4636;   // 2
    float4* red  = (float4*)(scr + 4640);  // 256 float4

    const int tid = threadIdx.x;
    const int wid = tid >> 5, lane = tid & 31;

    a0[tid] = audio[tid]; t0[tid] = text[tid];
    __syncthreads();

    gemv_fix<true,  true >(a0, W_pa, 256, 256, b_pa, x0, red);
    gemv_fix<true,  true >(t0, W_pt, 256, 256, b_pt, x1, red);
    gemv_fix<false, false>(x0, W_g1, 512, 256, nullptr, xs1,       red);
    gemv_fix<false, false>(x1, W_g1, 512, 256, nullptr, xs1 + 512, red);

    // e_src1/e_dst1: 8 warp reductions. wid: r=bit0, h=bit1, dst=bit2
    {
        int r = wid & 1, h = (wid >> 1) & 1, isdst = wid >> 2;
        const float* av = isdst ? ad1 : as1;
        float p = 0.f;
        for (int c = lane; c < 256; c += 32) p += xs1[r * 512 + h * 256 + c] * av[h * 256 + c];
#pragma unroll
        for (int o = 16; o; o >>= 1) p += __shfl_xor_sync(0xffffffffu, p, o);
        if (lane == 0) sc[wid] = p;
    }
    __syncthreads();
    if (tid == 0) {
        for (int t = 0; t < 2; t++)
            for (int h = 0; h < 2; h++) {
                float l0 = lrelu(sc[(h << 1) | 0] + sc[4 + ((h << 1) | t)]);
                float l1 = lrelu(sc[(h << 1) | 1] + sc[4 + ((h << 1) | t)]);
                float mx = fmaxf(l0, l1);
                float e0 = expf(l0 - mx), e1 = expf(l1 - mx);
                float inv = 1.f / (e0 + e1);
                al1[(t * 2 + 0) * 2 + h] = e0 * inv;
                al1[(t * 2 + 1) * 2 + h] = e1 * inv;
            }
    }
    __syncthreads();
    for (int idx = tid; idx < 1024; idx += 256) {
        int t = idx >> 9, j = idx & 511, h = j >> 8;
        float v = al1[(t * 2 + 0) * 2 + h] * xs1[j] + al1[(t * 2 + 1) * 2 + h] * xs1[512 + j] + b_g1[j];
        y1[t * 512 + j] = fmaxf(v, 0.f);
    }
    __syncthreads();

    gemv_fix<false, false>(y1,       W_g2, 256, 512, nullptr, xs2,       red);
    gemv_fix<false, false>(y1 + 512, W_g2, 256, 512, nullptr, xs2 + 256, red);

    if (wid < 4) {
        int r = wid & 1, isdst = wid >> 1;
        const float* av = isdst ? ad2 : as2;
        float p = 0.f;
        for (int c = lane; c < 256; c += 32) p += xs2[r * 256 + c] * av[c];
#pragma unroll
        for (int o = 16; o; o >>= 1) p += __shfl_xor_sync(0xffffffffu, p, o);
        if (lane == 0) sc[8 + wid] = p;
    }
    __syncthreads();
    if (tid == 0) {
        for (int t = 0; t < 2; t++) {
            float l0 = lrelu(sc[8 + 0] + sc[10 + t]);
            float l1 = lrelu(sc[8 + 1] + sc[10 + t]);
            float mx = fmaxf(l0, l1);
            float e0 = expf(l0 - mx), e1 = expf(l1 - mx);
            float inv = 1.f / (e0 + e1);
            al2[t * 2 + 0] = e0 * inv; al2[t * 2 + 1] = e1 * inv;
        }
    }
    __syncthreads();
    for (int idx = tid; idx < 512; idx += 256) {
        int t = idx >> 8, j = idx & 255;
        y2[t * 256 + j] = al2[t * 2 + 0] * xs2[j] + al2[t * 2 + 1] * xs2[256 + j] + b_g2[j];
    }
    __syncthreads();
    if (wid < 2) {
        float p = 0.f;
        for (int c = lane; c < 256; c += 32) p += y2[wid * 256 + c] * W_af[c];
#pragma unroll
        for (int o = 16; o; o >>= 1) p += __shfl_xor_sync(0xffffffffu, p, o);
        if (lane == 0) sc[12 + wid] = p + b_af[0];
    }
    __syncthreads();
    if (tid == 0) {
        float s0 = sc[12], s1 = sc[13];
        float mx = fmaxf(s0, s1);
        float e0 = expf(s0 - mx), e1 = expf(s1 - mx);
        float inv = 1.f / (e0 + e1);
        fw[0] = e0 * inv; fw[1] = e1 * inv;
    }
    __syncthreads();
    fused[tid] = fw[0] * y2[tid] + fw[1] * y2[256 + tid];
    __syncthreads();

    gemv_fix<false, true>(fused, W_fc, 256, 256, b_fc, obuf, red);
    out[tid] = obuf[tid];
}

// ---------------------------------------------------------------------------
__global__ void __launch_bounds__(NTHR, 1)
fused_main(const float* __restrict__ audio, const float* __restrict__ text,
           const float* __restrict__ W_pa, const float* __restrict__ b_pa,
           const float* __restrict__ W_pt, const float* __restrict__ b_pt,
           const float* __restrict__ W_g1, const float* __restrict__ as1,
           const float* __restrict__ ad1, const float* __restrict__ b_g1,
           const float* __restrict__ W_g2, const float* __restrict__ as2,
           const float* __restrict__ ad2, const float* __restrict__ b_g2,
           const float* __restrict__ W_af, const float* __restrict__ b_af,
           const float* __restrict__ W_fc, const float* __restrict__ b_fc,
           float* __restrict__ out)
{
    extern __shared__ float smem[];
    float* sY1 = smem + OFF_Y1;
    float* sND = smem + OFF_ND;
    float* sW  = smem + OFF_W;
    float* sS  = smem + OFF_S;
    float* sWt = smem + OFF_WT;

    const int tid = threadIdx.x;
    const int b0  = blockIdx.x * MB;

    // stage 0: inputs -> sY1 rows 0-31 (audio), rows 32-63 (text)
    {
        const float4* gA = (const float4*)(audio + (size_t)b0 * H);
        const float4* gT = (const float4*)(text  + (size_t)b0 * H);
        float4* sA = (float4*)sY1;
        float4* sT = (float4*)(sY1 + 8192);
#pragma unroll
        for (int j = 0; j < 8; j++) { int f = tid + (j << 8); sA[f] = gA[f]; sT[f] = gT[f]; }
    }
    // (gemm_dual prologue __syncthreads orders the stores above)

    // stage 1: dual-weight projection, 64 rows, interleaved -> sND.
    gemm_dual(sY1, W_pa, W_pt, b_pa, b_pt, sND, sY1 + 16384);

    // stage 2: GAT1 identity path, N=512 in two 256-col chunks -> sY1 (64 rows)
    gemm_tile<16, true >(sND, 256, 256, W_g1, 512, 0,   b_g1, sY1, 512, 1, 0, sW);
    gemm_tile<16, true >(sND, 256, 256, W_g1, 512, 256, b_g1, sY1, 512, 1, 0, sW);
    // stage 3: GAT2 identity path (no relu) -> sND (y2, 64 rows)
    gemm_tile<16, false>(sY1, 512, 512, W_g2, 256, 0,   b_g2, sND, 256, 1, 0, sW);
    __syncthreads();

    // stage 4: attention scores s[r] = y2[r] . W_af + b_af (8 warps x 8 rows)
    {
        const int wid = tid >> 5, lane = tid & 31;
#pragma unroll
        for (int rr = 0; rr < 8; rr++) {
            int r = wid * 8 + rr;
            const float* yr = sND + r * 256;
            float p = 0.f;
#pragma unroll
            for (int j = 0; j < 8; j++) p += yr[lane + (j << 5)] * W_af[lane + (j << 5)];
#pragma unroll
            for (int o = 16; o; o >>= 1) p += __shfl_xor_sync(0xffffffffu, p, o);
            if (lane == 0) sS[r] = p + b_af[0];
        }
    }
    __syncthreads();
    if (tid < MB) {
        float s0 = sS[2 * tid], s1 = sS[2 * tid + 1];
        float mx = fmaxf(s0, s1);
        float e0 = expf(s0 - mx), e1 = expf(s1 - mx);
        float inv = 1.f / (e0 + e1);
        sWt[2 * tid]     = e0 * inv;
        sWt[2 * tid + 1] = e1 * inv;
    }
    __syncthreads();

    // fuse: fused[m] = wa*y2[2m] + wt*y2[2m+1]  -> sY1 rows m (stride 256)
#pragma unroll
    for (int j = 0; j < 8; j++) {
        int f  = tid + (j << 8);          // float4 index, 0..2047
        int m  = f >> 6;
        int n4 = f & 63;
        float wa = sWt[2 * m], wt = sWt[2 * m + 1];
        float4 va = ((const float4*)(sND + (2 * m) * 256))[n4];
        float4 vt = ((const float4*)(sND + (2 * m + 1) * 256))[n4];
        ((float4*)(sY1 + m * 256))[n4] =
            make_float4(wa * va.x + wt * vt.x, wa * va.y + wt * vt.y,
                        wa * va.z + wt * vt.z, wa * va.w + wt * vt.w);
    }
    // stage 5: output projection, 32 rows (TM=8) -> global
    gemm_tile<8, false>(sY1, 256, 256, W_fc, 256, 0, b_fc,
                        out + (size_t)b0 * H, 256, 1, 0, sW);

    // block 0: recompute true GAT attention for batch 0, overwrite out[0].
    if (blockIdx.x == 0) {
        __syncthreads();
        fixup_b0(sND, audio, text, W_pa, b_pa, W_pt, b_pt,
                 W_g1, as1, ad1, b_g1, W_g2, as2, ad2, b_g2,
                 W_af, b_af, W_fc, b_fc, out);
    }
}

// ---------------------------------------------------------------------------
extern "C" void kernel_launch(void* const* d_in, const int* in_sizes, int n_in,
                              void* d_out, int out_size)
{
    const float* audio = (const float*)d_in[0];
    const float* text  = (const float*)d_in[1];
    const float* W_pa  = (const float*)d_in[2];
    const float* b_pa  = (const float*)d_in[3];
    const float* W_pt  = (const float*)d_in[4];
    const float* b_pt  = (const float*)d_in[5];
    const float* W_g1  = (const float*)d_in[6];
    const float* as1   = (const float*)d_in[7];
    const float* ad1   = (const float*)d_in[8];
    const float* b_g1  = (const float*)d_in[9];
    const float* W_g2  = (const float*)d_in[10];
    const float* as2   = (const float*)d_in[11];
    const float* ad2   = (const float*)d_in[12];
    const float* b_g2  = (const float*)d_in[13];
    const float* W_af  = (const float*)d_in[14];
    const float* b_af  = (const float*)d_in[15];
    const float* W_fc  = (const float*)d_in[16];
    const float* b_fc  = (const float*)d_in[17];
    float* out = (float*)d_out;

    const int batch = in_sizes[0] / H;           // 65536
    const int grid  = batch / MB;                // 2048

    cudaFuncSetAttribute(fused_main, cudaFuncAttributeMaxDynamicSharedMemorySize,
                         SMEM_BYTES);

    fused_main<<<grid, NTHR, SMEM_BYTES>>>(
        audio, text, W_pa, b_pa, W_pt, b_pt, W_g1, as1, ad1, b_g1,
        W_g2, as2, ad2, b_g2, W_af, b_af, W_fc, b_fc, out);
}

// round 9
// speedup vs baseline: 1.9499x; 1.0006x over previous
#include <cuda_runtime.h>
#include <cstdint>
#include <cstdio>

// ---------------------------------------------------------------------------
// GraphFusionLayerAtt: fully-fused fp32 pipeline (f32x2 packed FMA).
//   Col-split GEMM geometry: 4 row-groups x 2 col-groups, TM=16 rows/warp,
//   4 cols/thread -> halves the (binding) shared-crossbar weight traffic.
//   Identity GAT path for all batch elements; block 0 additionally recomputes
//   the true 2x2 GAT attention for nodes {0,1} inline and overwrites out[0].
// ---------------------------------------------------------------------------

typedef unsigned long long u64;

__device__ __forceinline__ u64 pack2(float x, float y) {
    u64 r; asm("mov.b64 %0, {%1, %2};" : "=l"(r) : "f"(x), "f"(y)); return r;
}
__device__ __forceinline__ u64 fma2(u64 a, u64 b, u64 c) {
    u64 d; asm("fma.rn.f32x2 %0, %1, %2, %3;" : "=l"(d) : "l"(a), "l"(b), "l"(c)); return d;
}
__device__ __forceinline__ float2 unpk(u64 v) {
    float2 f; asm("mov.b64 {%0, %1}, %2;" : "=f"(f.x), "=f"(f.y) : "l"(v)); return f;
}

static constexpr int H      = 256;
static constexpr int MB     = 32;     // batch elements per CTA
static constexpr int NTHR   = 256;    // 8 warps, 2 per SMSP
static constexpr int KT     = 16;     // k-tile for weight staging

// smem layout (floats)
static constexpr int OFF_Y1 = 0;          // 64x512 = 32768 (inputs+dualW / y1 / fused)
static constexpr int OFF_ND = 32768;      // 64x256 = 16384 (nodes, later y2, fixup scratch)
static constexpr int OFF_W  = 49152;      // 2 x 16x256 = 8192 (W double buffer)
static constexpr int OFF_S  = 57344;      // 64 scores
static constexpr int OFF_WT = 57408;      // 64 softmax weights
static constexpr int SMEM_FLOATS = 57472;
static constexpr int SMEM_BYTES  = SMEM_FLOATS * 4;   // 229,888 B

// ---------------------------------------------------------------------------
// cooperative load of a 16 x 256 weight tile (as float4s), 256 threads
__device__ __forceinline__ void ldgW(float4* pref, const float* __restrict__ gW,
                                     int ldw, int n0, int k0) {
    const int tid = threadIdx.x;
#pragma unroll
    for (int j = 0; j < 4; j++) {
        int f  = tid + (j << 8);          // 0..1023
        int kk = f >> 6;                  // 0..15
        int n  = (f & 63) << 2;           // 0..252
        pref[j] = *(const float4*)(gW + (size_t)(k0 + kk) * ldw + n0 + n);
    }
}
__device__ __forceinline__ void stsW(float* sW, const float4* pref) {
    const int tid = threadIdx.x;
#pragma unroll
    for (int j = 0; j < 4; j++) {
        int f = tid + (j << 8);
        ((float4*)sW)[f] = pref[j];       // linear layout == kk*256 + n
    }
}
// dual-tile variant: loads 16x256 tiles of BOTH Wa and Wb (8192 floats)
__device__ __forceinline__ void ldgW_dual(float4* pref, const float* __restrict__ gWa,
                                          const float* __restrict__ gWb, int k0) {
    const int tid = threadIdx.x;
#pragma unroll
    for (int j = 0; j < 8; j++) {
        int f    = tid + (j << 8);        // 0..2047
        int half = f >> 10;
        int f2   = f & 1023;
        int kk   = f2 >> 6;
        int n    = (f2 & 63) << 2;
        const float* W = half ? gWb : gWa;
        pref[j] = *(const float4*)(W + (size_t)(k0 + kk) * 256 + n);
    }
}
__device__ __forceinline__ void stsW_dual(float* buf, const float4* pref) {
    const int tid = threadIdx.x;
#pragma unroll
    for (int j = 0; j < 8; j++) {
        int f = tid + (j << 8);
        ((float4*)buf)[f] = pref[j];      // [0:4096)=Wa tile, [4096:8192)=Wb tile
    }
}

// ---------------------------------------------------------------------------
// Col-split GEMM stage: Y[r, n0..n0+256) = act( X[r,:] @ W[:, n0..n0+256) + b )
// Warp w: row-group = w>>1 (TM rows), col-group = w&1 (128 cols, 4/thread).
// Weight LDS halved vs full-width warps (each tile half read by 4 warps).
template <int TM, bool RELU>
__device__ __forceinline__ void gemm_tile(
    const float* __restrict__ sX, int ldx, int K,
    const float* __restrict__ gW, int ldw, int n0,
    const float* __restrict__ gB,
    float* __restrict__ Y, int ldy, int rowStride, int rowBase,
    float* __restrict__ sW)
{
    const int tid  = threadIdx.x;
    const int warp = tid >> 5;
    const int lane = tid & 31;
    const int rb   = (warp >> 1) * TM;
    const int ncol = ((warp & 1) << 7) | (lane << 2);   // 4 cols per thread

    float4 bb = *(const float4*)(gB + n0 + ncol);
    u64 acc[TM][2];
    {
        u64 b0 = pack2(bb.x, bb.y), b1 = pack2(bb.z, bb.w);
#pragma unroll
        for (int i = 0; i < TM; i++) { acc[i][0] = b0; acc[i][1] = b1; }
    }

    const int NT = K >> 4;
    float4 pref[4];
    ldgW(pref, gW, ldw, n0, 0);
    stsW(sW, pref);
    if (NT > 1) ldgW(pref, gW, ldw, n0, KT);
    __syncthreads();

    for (int kt = 0; kt < NT; kt++) {
        const float* sWc = sW + ((kt & 1) ? 4096 : 0);
        const float* sXk = sX + (kt << 4);
#pragma unroll
        for (int kk = 0; kk < KT; kk += 4) {
            float4 xv[TM];
#pragma unroll
            for (int i = 0; i < TM; i++)
                xv[i] = *(const float4*)(sXk + (rb + i) * ldx + kk);
#pragma unroll
            for (int dk = 0; dk < 4; dk++) {
                ulonglong2 wv = *(const ulonglong2*)(sWc + ((kk + dk) << 8) + ncol);
#pragma unroll
                for (int i = 0; i < TM; i++) {
                    float xs = (dk == 0) ? xv[i].x : (dk == 1) ? xv[i].y
                             : (dk == 2) ? xv[i].z : xv[i].w;
                    u64 xb = pack2(xs, xs);
                    acc[i][0] = fma2(xb, wv.x, acc[i][0]);
                    acc[i][1] = fma2(xb, wv.y, acc[i][1]);
                }
            }
        }
        if (kt + 1 < NT) {
            stsW(sW + (((kt + 1) & 1) ? 4096 : 0), pref);
            if (kt + 2 < NT) ldgW(pref, gW, ldw, n0, (kt + 2) << 4);
        }
        __syncthreads();
    }

#pragma unroll
    for (int i = 0; i < TM; i++) {
        int row = rowBase + (rb + i) * rowStride;
        float2 p0 = unpk(acc[i][0]), p1 = unpk(acc[i][1]);
        if (RELU) {
            p0.x = fmaxf(p0.x, 0.f); p0.y = fmaxf(p0.y, 0.f);
            p1.x = fmaxf(p1.x, 0.f); p1.y = fmaxf(p1.y, 0.f);
        }
        *(float4*)(Y + (size_t)row * ldy + n0 + ncol) = make_float4(p0.x, p0.y, p1.x, p1.y);
    }
}

// ---------------------------------------------------------------------------
// Stage-1 dual-weight GEMM (col-split): rows 0-31 audio (W_pa), 32-63 text
// (W_pt); TM=16, relu, output interleaved into sND (audio m -> row 2m,
// text m -> 2m+1). Weight tiles double-buffered in sWbig (2 x 8192 floats).
__device__ __forceinline__ void gemm_dual(
    const float* __restrict__ sX,                    // 64 x 256
    const float* __restrict__ gWa, const float* __restrict__ gWb,
    const float* __restrict__ bA,  const float* __restrict__ bB,
    float* __restrict__ Y,                           // sND, ld 256
    float* __restrict__ sWbig)
{
    const int tid  = threadIdx.x;
    const int warp = tid >> 5;
    const int lane = tid & 31;
    const int rowg = warp >> 1;
    const int rb   = rowg * 16;
    const int ncol = ((warp & 1) << 7) | (lane << 2);
    const bool sel = rowg >= 2;                      // row-groups 2,3: text / W_pt

    const float* gB = sel ? bB : bA;
    float4 bb = *(const float4*)(gB + ncol);
    u64 acc[16][2];
    {
        u64 b0 = pack2(bb.x, bb.y), b1 = pack2(bb.z, bb.w);
#pragma unroll
        for (int i = 0; i < 16; i++) { acc[i][0] = b0; acc[i][1] = b1; }
    }

    const int NT = 16;                               // K = 256
    float4 pref[8];
    ldgW_dual(pref, gWa, gWb, 0);
    stsW_dual(sWbig, pref);
    ldgW_dual(pref, gWa, gWb, KT);
    __syncthreads();

    const int wsel = sel ? 4096 : 0;
    for (int kt = 0; kt < NT; kt++) {
        const float* sWc = sWbig + ((kt & 1) ? 8192 : 0) + wsel;
        const float* sXk = sX + (kt << 4);
#pragma unroll
        for (int kk = 0; kk < KT; kk += 4) {
            float4 xv[16];
#pragma unroll
            for (int i = 0; i < 16; i++)
                xv[i] = *(const float4*)(sXk + (rb + i) * 256 + kk);
#pragma unroll
            for (int dk = 0; dk < 4; dk++) {
                ulonglong2 wv = *(const ulonglong2*)(sWc + ((kk + dk) << 8) + ncol);
#pragma unroll
                for (int i = 0; i < 16; i++) {
                    float xs = (dk == 0) ? xv[i].x : (dk == 1) ? xv[i].y
                             : (dk == 2) ? xv[i].z : xv[i].w;
                    u64 xb = pack2(xs, xs);
                    acc[i][0] = fma2(xb, wv.x, acc[i][0]);
                    acc[i][1] = fma2(xb, wv.y, acc[i][1]);
                }
            }
        }
        if (kt + 1 < NT) {
            stsW_dual(sWbig + (((kt + 1) & 1) ? 8192 : 0), pref);
            if (kt + 2 < NT) ldgW_dual(pref, gWa, gWb, (kt + 2) << 4);
        }
        __syncthreads();
    }

    // epilogue: relu + interleave (audio row r -> node 2r; text r -> 2(r-32)+1)
    const int rowBase = sel ? (((rb - 32) << 1) | 1) : (rb << 1);
#pragma unroll
    for (int i = 0; i < 16; i++) {
        int row = rowBase + (i << 1);
        float2 p0 = unpk(acc[i][0]), p1 = unpk(acc[i][1]);
        p0.x = fmaxf(p0.x, 0.f); p0.y = fmaxf(p0.y, 0.f);
        p1.x = fmaxf(p1.x, 0.f); p1.y = fmaxf(p1.y, 0.f);
        *(float4*)(Y + row * 256 + ncol) = make_float4(p0.x, p0.y, p1.x, p1.y);
    }
}

// ---------------------------------------------------------------------------
// Batch-0 fixup helpers (run by block 0 only, 256 threads, smem scratch)
// ---------------------------------------------------------------------------
__device__ __forceinline__ float lrelu(float x) { return x > 0.f ? x : 0.2f * x; }

// x: smem [K]; W: global row-major [K x N]; out: smem [N]. 256 threads.
template <bool RELU, bool BIAS>
__device__ __forceinline__ void gemv_fix(
    const float* __restrict__ xs, const float* __restrict__ W,
    int N, int K, const float* __restrict__ gB,
    float* __restrict__ out, float4* __restrict__ red)
{
    const int tid = threadIdx.x;
    const int N4  = N >> 2;
    const int S   = 256 / N4;             // k-splits
    const int g   = tid & (N4 - 1);
    const int s   = tid / N4;
    const int kps = K / S;

    float4 acc = make_float4(0.f, 0.f, 0.f, 0.f);
    const float* Wp = W + (size_t)(s * kps) * N + (g << 2);
    const float* xp = xs + s * kps;
#pragma unroll 8
    for (int k = 0; k < kps; k++) {
        float  xv = xp[k];
        float4 w  = *(const float4*)(Wp + (size_t)k * N);
        acc.x += xv * w.x; acc.y += xv * w.y;
        acc.z += xv * w.z; acc.w += xv * w.w;
    }
    red[tid] = acc;
    __syncthreads();
    if (s == 0) {
        for (int t = 1; t < S; t++) {
            float4 o = red[t * N4 + g];
            acc.x += o.x; acc.y += o.y; acc.z += o.z; acc.w += o.w;
        }
        if (BIAS) {
            float4 b = *(const float4*)(gB + (g << 2));
            acc.x += b.x; acc.y += b.y; acc.z += b.z; acc.w += b.w;
        }
        if (RELU) {
            acc.x = fmaxf(acc.x, 0.f); acc.y = fmaxf(acc.y, 0.f);
            acc.z = fmaxf(acc.z, 0.f); acc.w = fmaxf(acc.w, 0.f);
        }
        ((float4*)out)[g] = acc;
    }
    __syncthreads();
}

__device__ void fixup_b0(
    float* __restrict__ scr,              // >= 5664 floats of smem scratch
    const float* __restrict__ audio, const float* __restrict__ text,
    const float* __restrict__ W_pa, const float* __restrict__ b_pa,
    const float* __restrict__ W_pt, const float* __restrict__ b_pt,
    const float* __restrict__ W_g1, const float* __restrict__ as1,
    const float* __restrict__ ad1, const float* __restrict__ b_g1,
    const float* __restrict__ W_g2, const float* __restrict__ as2,
    const float* __restrict__ ad2, const float* __restrict__ b_g2,
    const float* __restrict__ W_af, const float* __restrict__ b_af,
    const float* __restrict__ W_fc, const float* __restrict__ b_fc,
    float* __restrict__ out)
{
    float* a0    = scr;          // 256
    float* t0    = scr + 256;
    float* x0    = scr + 512;
    float* x1    = scr + 768;
    float* xs1   = scr + 1024;   // 2 x 512
    float* y1    = scr + 2048;   // 2 x 512
    float* xs2   = scr + 3072;   // 2 x 256
    float* y2    = scr + 3584;   // 2 x 256
    float* fused = scr + 4096;   // 256
    float* obuf  = scr + 4352;   // 256
    float* sc    = scr + 4608;   // 16
    float* al1   = scr + 4624;   // 8: [t][s][h]
    float* al2   = scr + 4632;   // 4: [t][s]
    float* fw    = scr + 4636;   // 2
    float4* red  = (float4*)(scr + 4640);  // 256 float4

    const int tid = threadIdx.x;
    const int wid = tid >> 5, lane = tid & 31;

    a0[tid] = audio[tid]; t0[tid] = text[tid];
    __syncthreads();

    gemv_fix<true,  true >(a0, W_pa, 256, 256, b_pa, x0, red);
    gemv_fix<true,  true >(t0, W_pt, 256, 256, b_pt, x1, red);
    gemv_fix<false, false>(x0, W_g1, 512, 256, nullptr, xs1,       red);
    gemv_fix<false, false>(x1, W_g1, 512, 256, nullptr, xs1 + 512, red);

    // e_src1/e_dst1: 8 warp reductions. wid: r=bit0, h=bit1, dst=bit2
    {
        int r = wid & 1, h = (wid >> 1) & 1, isdst = wid >> 2;
        const float* av = isdst ? ad1 : as1;
        float p = 0.f;
        for (int c = lane; c < 256; c += 32) p += xs1[r * 512 + h * 256 + c] * av[h * 256 + c];
#pragma unroll
        for (int o = 16; o; o >>= 1) p += __shfl_xor_sync(0xffffffffu, p, o);
        if (lane == 0) sc[wid] = p;
    }
    __syncthreads();
    if (tid == 0) {
        for (int t = 0; t < 2; t++)
            for (int h = 0; h < 2; h++) {
                float l0 = lrelu(sc[(h << 1) | 0] + sc[4 + ((h << 1) | t)]);
                float l1 = lrelu(sc[(h << 1) | 1] + sc[4 + ((h << 1) | t)]);
                float mx = fmaxf(l0, l1);
                float e0 = expf(l0 - mx), e1 = expf(l1 - mx);
                float inv = 1.f / (e0 + e1);
                al1[(t * 2 + 0) * 2 + h] = e0 * inv;
                al1[(t * 2 + 1) * 2 + h] = e1 * inv;
            }
    }
    __syncthreads();
    for (int idx = tid; idx < 1024; idx += 256) {
        int t = idx >> 9, j = idx & 511, h = j >> 8;
        float v = al1[(t * 2 + 0) * 2 + h] * xs1[j] + al1[(t * 2 + 1) * 2 + h] * xs1[512 + j] + b_g1[j];
        y1[t * 512 + j] = fmaxf(v, 0.f);
    }
    __syncthreads();

    gemv_fix<false, false>(y1,       W_g2, 256, 512, nullptr, xs2,       red);
    gemv_fix<false, false>(y1 + 512, W_g2, 256, 512, nullptr, xs2 + 256, red);

    if (wid < 4) {
        int r = wid & 1, isdst = wid >> 1;
        const float* av = isdst ? ad2 : as2;
        float p = 0.f;
        for (int c = lane; c < 256; c += 32) p += xs2[r * 256 + c] * av[c];
#pragma unroll
        for (int o = 16; o; o >>= 1) p += __shfl_xor_sync(0xffffffffu, p, o);
        if (lane == 0) sc[8 + wid] = p;
    }
    __syncthreads();
    if (tid == 0) {
        for (int t = 0; t < 2; t++) {
            float l0 = lrelu(sc[8 + 0] + sc[10 + t]);
            float l1 = lrelu(sc[8 + 1] + sc[10 + t]);
            float mx = fmaxf(l0, l1);
            float e0 = expf(l0 - mx), e1 = expf(l1 - mx);
            float inv = 1.f / (e0 + e1);
            al2[t * 2 + 0] = e0 * inv; al2[t * 2 + 1] = e1 * inv;
        }
    }
    __syncthreads();
    for (int idx = tid; idx < 512; idx += 256) {
        int t = idx >> 8, j = idx & 255;
        y2[t * 256 + j] = al2[t * 2 + 0] * xs2[j] + al2[t * 2 + 1] * xs2[256 + j] + b_g2[j];
    }
    __syncthreads();
    if (wid < 2) {
        float p = 0.f;
        for (int c = lane; c < 256; c += 32) p += y2[wid * 256 + c] * W_af[c];
#pragma unroll
        for (int o = 16; o; o >>= 1) p += __shfl_xor_sync(0xffffffffu, p, o);
        if (lane == 0) sc[12 + wid] = p + b_af[0];
    }
    __syncthreads();
    if (tid == 0) {
        float s0 = sc[12], s1 = sc[13];
        float mx = fmaxf(s0, s1);
        float e0 = expf(s0 - mx), e1 = expf(s1 - mx);
        float inv = 1.f / (e0 + e1);
        fw[0] = e0 * inv; fw[1] = e1 * inv;
    }
    __syncthreads();
    fused[tid] = fw[0] * y2[tid] + fw[1] * y2[256 + tid];
    __syncthreads();

    gemv_fix<false, true>(fused, W_fc, 256, 256, b_fc, obuf, red);
    out[tid] = obuf[tid];
}

// ---------------------------------------------------------------------------
__global__ void __launch_bounds__(NTHR, 1)
fused_main(const float* __restrict__ audio, const float* __restrict__ text,
           const float* __restrict__ W_pa, const float* __restrict__ b_pa,
           const float* __restrict__ W_pt, const float* __restrict__ b_pt,
           const float* __restrict__ W_g1, const float* __restrict__ as1,
           const float* __restrict__ ad1, const float* __restrict__ b_g1,
           const float* __restrict__ W_g2, const float* __restrict__ as2,
           const float* __restrict__ ad2, const float* __restrict__ b_g2,
           const float* __restrict__ W_af, const float* __restrict__ b_af,
           const float* __restrict__ W_fc, const float* __restrict__ b_fc,
           float* __restrict__ out)
{
    extern __shared__ float smem[];
    float* sY1 = smem + OFF_Y1;
    float* sND = smem + OFF_ND;
    float* sW  = smem + OFF_W;
    float* sS  = smem + OFF_S;
    float* sWt = smem + OFF_WT;

    const int tid = threadIdx.x;
    const int b0  = blockIdx.x * MB;

    // stage 0: inputs -> sY1 rows 0-31 (audio), rows 32-63 (text)
    {
        const float4* gA = (const float4*)(audio + (size_t)b0 * H);
        const float4* gT = (const float4*)(text  + (size_t)b0 * H);
        float4* sA = (float4*)sY1;
        float4* sT = (float4*)(sY1 + 8192);
#pragma unroll
        for (int j = 0; j < 8; j++) { int f = tid + (j << 8); sA[f] = gA[f]; sT[f] = gT[f]; }
    }
    // (gemm_dual prologue __syncthreads orders the stores above)

    // stage 1: dual-weight projection, 64 rows, interleaved -> sND.
    gemm_dual(sY1, W_pa, W_pt, b_pa, b_pt, sND, sY1 + 16384);

    // stage 2: GAT1 identity path, N=512 in two 256-col chunks -> sY1 (64 rows)
    gemm_tile<16, true >(sND, 256, 256, W_g1, 512, 0,   b_g1, sY1, 512, 1, 0, sW);
    gemm_tile<16, true >(sND, 256, 256, W_g1, 512, 256, b_g1, sY1, 512, 1, 0, sW);
    // stage 3: GAT2 identity path (no relu) -> sND (y2, 64 rows)
    gemm_tile<16, false>(sY1, 512, 512, W_g2, 256, 0,   b_g2, sND, 256, 1, 0, sW);
    __syncthreads();

    // stage 4: attention scores s[r] = y2[r] . W_af + b_af (8 warps x 8 rows)
    {
        const int wid = tid >> 5, lane = tid & 31;
#pragma unroll
        for (int rr = 0; rr < 8; rr++) {
            int r = wid * 8 + rr;
            const float* yr = sND + r * 256;
            float p = 0.f;
#pragma unroll
            for (int j = 0; j < 8; j++) p += yr[lane + (j << 5)] * W_af[lane + (j << 5)];
#pragma unroll
            for (int o = 16; o; o >>= 1) p += __shfl_xor_sync(0xffffffffu, p, o);
            if (lane == 0) sS[r] = p + b_af[0];
        }
    }
    __syncthreads();
    if (tid < MB) {
        float s0 = sS[2 * tid], s1 = sS[2 * tid + 1];
        float mx = fmaxf(s0, s1);
        float e0 = expf(s0 - mx), e1 = expf(s1 - mx);
        float inv = 1.f / (e0 + e1);
        sWt[2 * tid]     = e0 * inv;
        sWt[2 * tid + 1] = e1 * inv;
    }
    __syncthreads();

    // fuse: fused[m] = wa*y2[2m] + wt*y2[2m+1]  -> sY1 rows m (stride 256)
#pragma unroll
    for (int j = 0; j < 8; j++) {
        int f  = tid + (j << 8);          // float4 index, 0..2047
        int m  = f >> 6;
        int n4 = f & 63;
        float wa = sWt[2 * m], wt = sWt[2 * m + 1];
        float4 va = ((const float4*)(sND + (2 * m) * 256))[n4];
        float4 vt = ((const float4*)(sND + (2 * m + 1) * 256))[n4];
        ((float4*)(sY1 + m * 256))[n4] =
            make_float4(wa * va.x + wt * vt.x, wa * va.y + wt * vt.y,
                        wa * va.z + wt * vt.z, wa * va.w + wt * vt.w);
    }
    // stage 5: output projection, 32 rows (TM=8) -> global
    gemm_tile<8, false>(sY1, 256, 256, W_fc, 256, 0, b_fc,
                        out + (size_t)b0 * H, 256, 1, 0, sW);

    // block 0: recompute true GAT attention for batch 0, overwrite out[0].
    if (blockIdx.x == 0) {
        __syncthreads();
        fixup_b0(sND, audio, text, W_pa, b_pa, W_pt, b_pt,
                 W_g1, as1, ad1, b_g1, W_g2, as2, ad2, b_g2,
                 W_af, b_af, W_fc, b_fc, out);
    }
}

// ---------------------------------------------------------------------------
extern "C" void kernel_launch(void* const* d_in, const int* in_sizes, int n_in,
                              void* d_out, int out_size)
{
    const float* audio = (const float*)d_in[0];
    const float* text  = (const float*)d_in[1];
    const float* W_pa  = (const float*)d_in[2];
    const float* b_pa  = (const float*)d_in[3];
    const float* W_pt  = (const float*)d_in[4];
    const float* b_pt  = (const float*)d_in[5];
    const float* W_g1  = (const float*)d_in[6];
    const float* as1   = (const float*)d_in[7];
    const float* ad1   = (const float*)d_in[8];
    const float* b_g1  = (const float*)d_in[9];
    const float* W_g2  = (const float*)d_in[10];
    const float* as2   = (const float*)d_in[11];
    const float* ad2   = (const float*)d_in[12];
    const float* b_g2  = (const float*)d_in[13];
    const float* W_af  = (const float*)d_in[14];
    const float* b_af  = (const float*)d_in[15];
    const float* W_fc  = (const float*)d_in[16];
    const float* b_fc  = (const float*)d_in[17];
    float* out = (float*)d_out;

    const int batch = in_sizes[0] / H;           // 65536
    const int grid  = batch / MB;                // 2048

    cudaFuncSetAttribute(fused_main, cudaFuncAttributeMaxDynamicSharedMemorySize,
                         SMEM_BYTES);

    fused_main<<<grid, NTHR, SMEM_BYTES>>>(
        audio, text, W_pa, b_pa, W_pt, b_pt, W_g1, as1, ad1, b_g1,
        W_g2, as2, ad2, b_g2, W_af, b_af, W_fc, b_fc, out);
}